// round 14
// baseline (speedup 1.0000x reference)
#include <cuda_runtime.h>
#include <cuda_bf16.h>
#include <cuda_fp16.h>
#include <math.h>
#include <stdint.h>

#define B 8
#define C 384
#define HW 128
#define N 16384
#define HEADS 8
#define HD 48
#define M3 1152
#define KSPLIT 32
#define EPSV 1e-12f

#define BM 64
#define BN 128
#define BK 32
#define APAD 40
#define BPAD 136

// ---------------- scratch ----------------
__device__ __align__(16) __half g_pw[(size_t)B * M3 * N];
__device__ __align__(16) __half g_dw[(size_t)B * M3 * N];
__device__ __align__(16) __half g_Xh[(size_t)B * C * N];
__device__ __align__(16) __half g_avh[(size_t)B * C * N];
__device__ __align__(16) __half g_Whi[M3 * C];
__device__ __align__(16) __half g_Wlo[M3 * C];
__device__ __align__(16) __half g_Phi[C * C];
__device__ __align__(16) __half g_Plo[C * C];
__device__ float g_ball[M3];
__device__ float g_DWall[M3 * 9];
__device__ float g_dwball[M3];
__device__ float g_norm2[B * 2 * C];
__device__ float g_dcp[B * C];
__device__ float g_attn_part[(size_t)B * HEADS * KSPLIT * HD * HD];
__device__ float g_attn[(size_t)B * HEADS * HD * HD];

__device__ __forceinline__ void split2h(float x, __half& h, __half& l) {
    h = __float2half(x);
    l = __float2half(x - __half2float(h));
}

// ---------------- PTX helpers ----------------
__device__ __forceinline__ void cpa16(uint32_t d, const void* s) {
    asm volatile("cp.async.cg.shared.global [%0], [%1], 16;\n" :: "r"(d), "l"(s));
}
__device__ __forceinline__ void cpa_commit() { asm volatile("cp.async.commit_group;\n"); }
__device__ __forceinline__ void cpa_wait3() { asm volatile("cp.async.wait_group 3;\n"); }
__device__ __forceinline__ void cpa_wait2() { asm volatile("cp.async.wait_group 2;\n"); }
__device__ __forceinline__ void cpa_wait1() { asm volatile("cp.async.wait_group 1;\n"); }
__device__ __forceinline__ void cpa_wait0() { asm volatile("cp.async.wait_group 0;\n"); }

__device__ __forceinline__ void ldsm4(uint32_t* r, uint32_t addr) {
    asm volatile("ldmatrix.sync.aligned.m8n8.x4.shared.b16 {%0,%1,%2,%3}, [%4];"
                 : "=r"(r[0]), "=r"(r[1]), "=r"(r[2]), "=r"(r[3]) : "r"(addr));
}
__device__ __forceinline__ void ldsm2t(uint32_t* r, uint32_t addr) {
    asm volatile("ldmatrix.sync.aligned.m8n8.x2.trans.shared.b16 {%0,%1}, [%2];"
                 : "=r"(r[0]), "=r"(r[1]) : "r"(addr));
}
__device__ __forceinline__ void mma16816h(float* c, const uint32_t* a, const uint32_t* b) {
    asm volatile("mma.sync.aligned.m16n8k16.row.col.f32.f16.f16.f32 "
                 "{%0,%1,%2,%3}, {%4,%5,%6,%7}, {%8,%9}, {%0,%1,%2,%3};\n"
                 : "+f"(c[0]), "+f"(c[1]), "+f"(c[2]), "+f"(c[3])
                 : "r"(a[0]), "r"(a[1]), "r"(a[2]), "r"(a[3]), "r"(b[0]), "r"(b[1]));
}

// ---------------- weight packing ----------------
__global__ void pack_weights(
    const float* __restrict__ wq, const float* __restrict__ wqb,
    const float* __restrict__ wqd, const float* __restrict__ wqdb,
    const float* __restrict__ wk, const float* __restrict__ wkb,
    const float* __restrict__ wkd, const float* __restrict__ wkdb,
    const float* __restrict__ wv, const float* __restrict__ wvb,
    const float* __restrict__ wvd, const float* __restrict__ wvdb,
    const float* __restrict__ prj) {
    int i = blockIdx.x * blockDim.x + threadIdx.x;
    if (i < C * C) {
        __half h, l;
        split2h(wq[i], h, l);  g_Whi[i] = h;              g_Wlo[i] = l;
        split2h(wk[i], h, l);  g_Whi[C * C + i] = h;      g_Wlo[C * C + i] = l;
        split2h(wv[i], h, l);  g_Whi[2 * C * C + i] = h;  g_Wlo[2 * C * C + i] = l;
        split2h(prj[i], h, l); g_Phi[i] = h;              g_Plo[i] = l;
    }
    if (i < C * 9) {
        g_DWall[i] = wqd[i];
        g_DWall[C * 9 + i] = wkd[i];
        g_DWall[2 * C * 9 + i] = wvd[i];
    }
    if (i < C) {
        g_ball[i] = wqb[i];  g_ball[C + i] = wkb[i];  g_ball[2 * C + i] = wvb[i];
        g_dwball[i] = wqdb[i]; g_dwball[C + i] = wkdb[i]; g_dwball[2 * C + i] = wvdb[i];
    }
    if (i < B * 2 * C) g_norm2[i] = 0.f;
}

// ---------------- input -> fp16 ----------------
__global__ void split_kernel(const float* __restrict__ x, __half* __restrict__ xh, int n4) {
    int i = blockIdx.x * blockDim.x + threadIdx.x;
    if (i >= n4) return;
    float4 v = ((const float4*)x)[i];
    ((__half2*)xh)[i * 2] = __floats2half2_rn(v.x, v.y);
    ((__half2*)xh)[i * 2 + 1] = __floats2half2_rn(v.z, v.w);
}

// ---------------- degrade-class MLP ----------------
__global__ void dcp_kernel(const float* __restrict__ d_c,
                           const float* __restrict__ w1, const float* __restrict__ b1,
                           const float* __restrict__ w2, const float* __restrict__ b2) {
    __shared__ float hdn[48];
    int b = blockIdx.x;
    int t = threadIdx.x;
    if (t < 48) {
        float s = b1[t];
        #pragma unroll
        for (int i = 0; i < 3; i++) s += d_c[b * 3 + i] * w1[i * 48 + t];
        float x = s;
        float inner = 0.7978845608028654f * (x + 0.044715f * x * x * x);
        hdn[t] = 0.5f * x * (1.0f + tanhf(inner));
    }
    __syncthreads();
    float s = b2[t];
    #pragma unroll 8
    for (int j = 0; j < 48; j++) s += hdn[j] * w2[j * C + t];
    g_dcp[b * C + t] = s;
}

// ---------------- fp16 GEMM: 64x128 tile, 4-stage cp.async, 3 CTAs/SM ----------------
#define A_STRIDE (BM * APAD)
#define B_STRIDE (BK * BPAD)
#define STG_ELEMS (2 * A_STRIDE + B_STRIDE)
#define OFF_ALO A_STRIDE
#define OFF_BH  (2 * A_STRIDE)
#define NSTG 4
#define GEMM_SMEM (NSTG * STG_ELEMS * 2)   // 75776 bytes

__global__ void __launch_bounds__(256, 3) gemm_tc_kernel(
    const __half* __restrict__ Whi, const __half* __restrict__ Wlo,
    const float* __restrict__ bias,
    const __half* __restrict__ Xh,
    float* __restrict__ Yf, __half* __restrict__ Yh, int M) {
    extern __shared__ __half sm[];

    int b = blockIdx.z;
    const __half* XB = Xh + (size_t)b * C * N;
    int n0 = blockIdx.x * BN, m0 = blockIdx.y * BM;
    int t = threadIdx.x, lane = t & 31, w = t >> 5;
    int wm = (w >> 2) * 32, wn = (w & 3) * 32;

    int aRow = t >> 2, aSeg = (t & 3) * 8;
    int bRow0 = (2 * t) >> 4, bSeg0 = ((2 * t) & 15) * 8;
    int bRow1 = (2 * t + 1) >> 4, bSeg1 = ((2 * t + 1) & 15) * 8;

    float acc[2][4][4];
    #pragma unroll
    for (int mi = 0; mi < 2; mi++)
        #pragma unroll
        for (int ni = 0; ni < 4; ni++)
            #pragma unroll
            for (int r = 0; r < 4; r++) acc[mi][ni][r] = 0.f;

    auto issue = [&](int k0, int st) {
        __half* base = sm + st * STG_ELEMS;
        cpa16((uint32_t)__cvta_generic_to_shared(base + aRow * APAD + aSeg),
              Whi + (size_t)(m0 + aRow) * C + k0 + aSeg);
        cpa16((uint32_t)__cvta_generic_to_shared(base + OFF_ALO + aRow * APAD + aSeg),
              Wlo + (size_t)(m0 + aRow) * C + k0 + aSeg);
        cpa16((uint32_t)__cvta_generic_to_shared(base + OFF_BH + bRow0 * BPAD + bSeg0),
              XB + (size_t)(k0 + bRow0) * N + n0 + bSeg0);
        cpa16((uint32_t)__cvta_generic_to_shared(base + OFF_BH + bRow1 * BPAD + bSeg1),
              XB + (size_t)(k0 + bRow1) * N + n0 + bSeg1);
        cpa_commit();
    };

    const int NIT = C / BK;   // 12
    issue(0, 0);
    issue(BK, 1);
    issue(2 * BK, 2);
    for (int it = 0; it < NIT; it++) {
        if (it + 3 < NIT) { issue((it + 3) * BK, (it + 3) % NSTG); cpa_wait3(); }
        else if (it + 2 < NIT) cpa_wait2();
        else if (it + 1 < NIT) cpa_wait1();
        else cpa_wait0();
        __syncthreads();
        __half* base = sm + (it % NSTG) * STG_ELEMS;
        __half* ah_s = base;
        __half* al_s = base + OFF_ALO;
        __half* bh_s = base + OFF_BH;
        #pragma unroll
        for (int kk = 0; kk < BK; kk += 16) {
            uint32_t bhf[4][2];
            #pragma unroll
            for (int ni = 0; ni < 4; ni++)
                ldsm2t(bhf[ni], (uint32_t)__cvta_generic_to_shared(
                    bh_s + (kk + (lane & 15)) * BPAD + wn + ni * 8));
            #pragma unroll
            for (int mi = 0; mi < 2; mi++) {
                uint32_t ahf[4], alf[4];
                ldsm4(ahf, (uint32_t)__cvta_generic_to_shared(
                    ah_s + (wm + mi * 16 + (lane & 15)) * APAD + kk + ((lane >> 4) << 3)));
                ldsm4(alf, (uint32_t)__cvta_generic_to_shared(
                    al_s + (wm + mi * 16 + (lane & 15)) * APAD + kk + ((lane >> 4) << 3)));
                #pragma unroll
                for (int ni = 0; ni < 4; ni++) {
                    mma16816h(acc[mi][ni], ahf, bhf[ni]);
                    mma16816h(acc[mi][ni], alf, bhf[ni]);
                }
            }
        }
        __syncthreads();
    }

    int r = lane >> 2;
    #pragma unroll
    for (int mi = 0; mi < 2; mi++) {
        int m1 = m0 + wm + mi * 16 + r;
        int m2 = m1 + 8;
        float b1 = bias[m1], b2 = bias[m2];
        #pragma unroll
        for (int ni = 0; ni < 4; ni++) {
            int col = n0 + wn + ni * 8 + (lane & 3) * 2;
            if (Yh) {
                __half* Yb = Yh + (size_t)b * (size_t)M * N;
                *(__half2*)&Yb[(size_t)m1 * N + col] =
                    __floats2half2_rn(acc[mi][ni][0] + b1, acc[mi][ni][1] + b1);
                *(__half2*)&Yb[(size_t)m2 * N + col] =
                    __floats2half2_rn(acc[mi][ni][2] + b2, acc[mi][ni][3] + b2);
            } else {
                float* Yb = Yf + (size_t)b * (size_t)M * N;
                *(float2*)&Yb[(size_t)m1 * N + col] =
                    make_float2(acc[mi][ni][0] + b1, acc[mi][ni][1] + b1);
                *(float2*)&Yb[(size_t)m2 * N + col] =
                    make_float2(acc[mi][ni][2] + b2, acc[mi][ni][3] + b2);
            }
        }
    }
}

// ---------------- depthwise 3x3: 32-row tiles, 512 threads, fp16 in/out, fused sumsq ----------------
__global__ void __launch_bounds__(512) dwconv_kernel(const __half* __restrict__ in,
                                                     __half* __restrict__ out) {
    __shared__ float s[34][132];
    __shared__ float red[16];
    int plane = blockIdx.y;
    int ch = plane % M3;
    int b = plane / M3;
    int y0 = blockIdx.x * 32;
    const __half* ip = in + (size_t)plane * N;
    __half* op = out + (size_t)plane * N;
    int tx = threadIdx.x, ty = threadIdx.y;   // (32, 16)
    int t = ty * 32 + tx;

    for (int i = t; i < 544; i += 512) {
        int r = i >> 4, c8 = i & 15;
        int gy = y0 - 1 + r;
        uint4 raw = make_uint4(0, 0, 0, 0);
        if (gy >= 0 && gy < HW) raw = *(const uint4*)(ip + gy * HW + c8 * 8);
        const __half2* hp = (const __half2*)&raw;
        #pragma unroll
        for (int k2 = 0; k2 < 4; k2++) {
            float2 f = __half22float2(hp[k2]);
            s[r][1 + c8 * 8 + k2 * 2] = f.x;
            s[r][1 + c8 * 8 + k2 * 2 + 1] = f.y;
        }
        if (c8 == 0) s[r][0] = 0.f;
        if (c8 == 15) s[r][129] = 0.f;
    }
    __syncthreads();

    float wgt[9];
    #pragma unroll
    for (int i = 0; i < 9; i++) wgt[i] = g_DWall[ch * 9 + i];
    float bsv = g_dwball[ch];

    float o[2][4];
    #pragma unroll
    for (int g = 0; g < 2; g++)
        #pragma unroll
        for (int j = 0; j < 4; j++) o[g][j] = bsv;
    #pragma unroll
    for (int rr = 0; rr < 3; rr++) {
        float w0 = wgt[rr * 3 + 0], w1 = wgt[rr * 3 + 1], w2 = wgt[rr * 3 + 2];
        #pragma unroll
        for (int g = 0; g < 2; g++) {
            float v[6];
            #pragma unroll
            for (int j = 0; j < 6; j++) v[j] = s[ty + g * 16 + rr][tx * 4 + j];
            #pragma unroll
            for (int j = 0; j < 4; j++)
                o[g][j] += w0 * v[j] + w1 * v[j + 1] + w2 * v[j + 2];
        }
    }
    float ss = 0.f;
    #pragma unroll
    for (int g = 0; g < 2; g++) {
        __half2 h0 = __floats2half2_rn(o[g][0], o[g][1]);
        __half2 h1 = __floats2half2_rn(o[g][2], o[g][3]);
        __half* dst = op + (y0 + ty + g * 16) * HW + tx * 4;
        *(__half2*)dst = h0;
        *(__half2*)(dst + 2) = h1;
        float2 f0 = __half22float2(h0), f1 = __half22float2(h1);
        ss += f0.x * f0.x + f0.y * f0.y + f1.x * f1.x + f1.y * f1.y;
    }

    if (ch < 2 * C) {
        #pragma unroll
        for (int off = 16; off > 0; off >>= 1)
            ss += __shfl_down_sync(0xffffffffu, ss, off);
        int wid = t >> 5;
        if ((t & 31) == 0) red[wid] = ss;
        __syncthreads();
        if (t == 0) {
            float tot = 0.f;
            #pragma unroll
            for (int i = 0; i < 16; i++) tot += red[i];
            atomicAdd(&g_norm2[b * 768 + ch], tot);
        }
    }
}

// ---------------- QK^T: single fp16 mma, split-K over tokens ----------------
#define QNT 64
#define QP 72
#define KP 56
__global__ void __launch_bounds__(192) qk_tc_kernel(const __half* __restrict__ dwbuf) {
    __shared__ __half qs[HD * QP];
    __shared__ __half ks[QNT * KP];
    __shared__ float redbuf[3 * 6 * 128];

    int bh = blockIdx.y;
    int b = bh >> 3, h = bh & 7;
    const __half* qp = dwbuf + ((size_t)b * M3 + h * HD) * N;
    const __half* kp = dwbuf + ((size_t)b * M3 + C + h * HD) * N;
    int n0 = blockIdx.x * (N / KSPLIT);
    int t = threadIdx.x, lane = t & 31, w = t >> 5;
    int mi = w % 3, kh = w / 3;

    float acc[6][4];
    #pragma unroll
    for (int ni = 0; ni < 6; ni++)
        #pragma unroll
        for (int r = 0; r < 4; r++) acc[ni][r] = 0.f;

    for (int s = 0; s < (N / KSPLIT) / QNT; s++) {
        int off = n0 + s * QNT;
        for (int i = t; i < HD * 8; i += 192) {
            int c = i >> 3, chk = (i & 7) * 8;
            *(uint4*)&qs[c * QP + chk] = *(const uint4*)(qp + (size_t)c * N + off + chk);
        }
        for (int i = t; i < HD * 32; i += 192) {
            int d = i >> 5, n2 = (i & 31) * 2;
            __half2 v = *(const __half2*)(kp + (size_t)d * N + off + n2);
            ks[(n2 + 0) * KP + d] = __low2half(v);
            ks[(n2 + 1) * KP + d] = __high2half(v);
        }
        __syncthreads();
        #pragma unroll
        for (int kk2 = 0; kk2 < 2; kk2++) {
            int kk = kh * 32 + kk2 * 16;
            uint32_t ahf[4];
            ldsm4(ahf, (uint32_t)__cvta_generic_to_shared(
                &qs[(mi * 16 + (lane & 15)) * QP + kk + ((lane >> 4) << 3)]));
            #pragma unroll
            for (int ni = 0; ni < 6; ni++) {
                uint32_t bhf[2];
                ldsm2t(bhf, (uint32_t)__cvta_generic_to_shared(
                    &ks[(kk + (lane & 15)) * KP + ni * 8]));
                mma16816h(acc[ni], ahf, bhf);
            }
        }
        __syncthreads();
    }

    if (kh == 1) {
        #pragma unroll
        for (int ni = 0; ni < 6; ni++)
            #pragma unroll
            for (int r = 0; r < 4; r++)
                redbuf[(mi * 6 + ni) * 128 + lane * 4 + r] = acc[ni][r];
    }
    __syncthreads();
    if (kh == 0) {
        float* outp = g_attn_part + ((size_t)bh * KSPLIT + blockIdx.x) * (HD * HD);
        #pragma unroll
        for (int ni = 0; ni < 6; ni++) {
            #pragma unroll
            for (int r = 0; r < 4; r++)
                acc[ni][r] += redbuf[(mi * 6 + ni) * 128 + lane * 4 + r];
            int c0 = mi * 16 + (lane >> 2);
            int d0 = ni * 8 + (lane & 3) * 2;
            outp[c0 * HD + d0]       = acc[ni][0];
            outp[c0 * HD + d0 + 1]   = acc[ni][1];
            outp[(c0 + 8) * HD + d0]     = acc[ni][2];
            outp[(c0 + 8) * HD + d0 + 1] = acc[ni][3];
        }
    }
}

// ---------------- combine, modulate, softmax ----------------
__global__ void softmax_kernel(const float* __restrict__ temp, const float* __restrict__ d_l) {
    __shared__ float S[HD * HD];
    int bh = blockIdx.x;
    int b = bh >> 3, h = bh & 7;
    int t = threadIdx.x;
    float tscale = temp[h] * d_l[b];
    for (int idx = t; idx < HD * HD; idx += 256) {
        const float* pp = g_attn_part + (size_t)bh * KSPLIT * (HD * HD) + idx;
        float s = 0.f;
        #pragma unroll
        for (int sp = 0; sp < KSPLIT; sp++) s += pp[(size_t)sp * (HD * HD)];
        int c = idx / HD, d = idx % HD;
        float nq = fmaxf(sqrtf(g_norm2[b * 768 + h * HD + c]), EPSV);
        float nk = fmaxf(sqrtf(g_norm2[b * 768 + C + h * HD + d]), EPSV);
        S[idx] = s / (nq * nk) * tscale * g_dcp[b * C + h * HD + c];
    }
    __syncthreads();
    if (t < HD) {
        float mx = -1e30f;
        for (int d = 0; d < HD; d++) mx = fmaxf(mx, S[t * HD + d]);
        float sum = 0.f;
        for (int d = 0; d < HD; d++) sum += expf(S[t * HD + d] - mx);
        float inv = 1.f / sum;
        for (int d = 0; d < HD; d++)
            g_attn[(size_t)bh * (HD * HD) + t * HD + d] = expf(S[t * HD + d] - mx) * inv;
    }
}

// ---------------- attn @ v: tensor-core (M=48, K=48), fp16 in/out ----------------
#define AVP 136
__global__ void __launch_bounds__(192) av_tc_kernel(const __half* __restrict__ dwbuf,
                                                    __half* __restrict__ oh) {
    __shared__ __half As[HD * 56];
    __shared__ __half vs[HD * AVP];
    int bh = blockIdx.y;
    int b = bh >> 3, h = bh & 7;
    const __half* vp = dwbuf + ((size_t)b * M3 + 2 * C + h * HD) * N;
    __half* op = oh + ((size_t)b * C + h * HD) * N;
    int t = threadIdx.x, lane = t & 31, w = t >> 5;
    int mi = w % 3, nh = w / 3;

    const float* ap = g_attn + (size_t)bh * (HD * HD);
    for (int i = t; i < HD * HD; i += 192) {
        int c = i / HD, d = i % HD;
        As[c * 56 + d] = __float2half(ap[i]);
    }
    __syncthreads();

    int n0 = blockIdx.x * 512;
    for (int chunk = 0; chunk < 4; chunk++) {
        int off = n0 + chunk * 128;
        for (int i = t; i < HD * 16; i += 192) {
            int d = i >> 4, c16 = (i & 15) * 8;
            *(uint4*)&vs[d * AVP + c16] = *(const uint4*)(vp + (size_t)d * N + off + c16);
        }
        __syncthreads();

        float acc[8][4];
        #pragma unroll
        for (int ni = 0; ni < 8; ni++)
            #pragma unroll
            for (int r = 0; r < 4; r++) acc[ni][r] = 0.f;

        #pragma unroll
        for (int kk2 = 0; kk2 < 3; kk2++) {
            int kk = kk2 * 16;
            uint32_t af[4];
            ldsm4(af, (uint32_t)__cvta_generic_to_shared(
                &As[(mi * 16 + (lane & 15)) * 56 + kk + ((lane >> 4) << 3)]));
            #pragma unroll
            for (int ni = 0; ni < 8; ni++) {
                uint32_t bf[2];
                ldsm2t(bf, (uint32_t)__cvta_generic_to_shared(
                    &vs[(kk + (lane & 15)) * AVP + nh * 64 + ni * 8]));
                mma16816h(acc[ni], af, bf);
            }
        }

        int r = lane >> 2;
        int c1 = mi * 16 + r, c2 = c1 + 8;
        #pragma unroll
        for (int ni = 0; ni < 8; ni++) {
            int col = off + nh * 64 + ni * 8 + (lane & 3) * 2;
            *(__half2*)&op[(size_t)c1 * N + col] = __floats2half2_rn(acc[ni][0], acc[ni][1]);
            *(__half2*)&op[(size_t)c2 * N + col] = __floats2half2_rn(acc[ni][2], acc[ni][3]);
        }
        __syncthreads();
    }
}

// ---------------- launch ----------------
extern "C" void kernel_launch(void* const* d_in, const int* in_sizes, int n_in,
                              void* d_out, int out_size) {
    const float* inputs  = (const float*)d_in[0];
    const float* d_c     = (const float*)d_in[1];
    const float* d_l     = (const float*)d_in[2];
    const float* temp    = (const float*)d_in[3];
    const float* prj_w   = (const float*)d_in[4];
    const float* prj_b   = (const float*)d_in[5];
    const float* dp_w1   = (const float*)d_in[6];
    const float* dp_b1   = (const float*)d_in[7];
    const float* dp_w2   = (const float*)d_in[8];
    const float* dp_b2   = (const float*)d_in[9];
    const float* wq_pw   = (const float*)d_in[10];
    const float* wq_pw_b = (const float*)d_in[11];
    const float* wq_dw   = (const float*)d_in[12];
    const float* wq_dw_b = (const float*)d_in[13];
    const float* wk_pw   = (const float*)d_in[14];
    const float* wk_pw_b = (const float*)d_in[15];
    const float* wk_dw   = (const float*)d_in[16];
    const float* wk_dw_b = (const float*)d_in[17];
    const float* wv_pw   = (const float*)d_in[18];
    const float* wv_pw_b = (const float*)d_in[19];
    const float* wv_dw   = (const float*)d_in[20];
    const float* wv_dw_b = (const float*)d_in[21];
    float* outp = (float*)d_out;

    __half *p_Whi, *p_Wlo, *p_Phi, *p_Plo, *p_Xh, *p_avh, *p_pw, *p_dw;
    float *p_ball;
    cudaGetSymbolAddress((void**)&p_Whi, g_Whi);
    cudaGetSymbolAddress((void**)&p_Wlo, g_Wlo);
    cudaGetSymbolAddress((void**)&p_Phi, g_Phi);
    cudaGetSymbolAddress((void**)&p_Plo, g_Plo);
    cudaGetSymbolAddress((void**)&p_Xh, g_Xh);
    cudaGetSymbolAddress((void**)&p_avh, g_avh);
    cudaGetSymbolAddress((void**)&p_ball, g_ball);
    cudaGetSymbolAddress((void**)&p_pw, g_pw);
    cudaGetSymbolAddress((void**)&p_dw, g_dw);

    cudaFuncSetAttribute(gemm_tc_kernel,
                         cudaFuncAttributeMaxDynamicSharedMemorySize, GEMM_SMEM);

    pack_weights<<<(C * C + 255) / 256, 256>>>(
        wq_pw, wq_pw_b, wq_dw, wq_dw_b,
        wk_pw, wk_pw_b, wk_dw, wk_dw_b,
        wv_pw, wv_pw_b, wv_dw, wv_dw_b, prj_w);

    dcp_kernel<<<B, C>>>(d_c, dp_w1, dp_b1, dp_w2, dp_b2);

    split_kernel<<<(B * C * N / 4 + 255) / 256, 256>>>(inputs, p_Xh, B * C * N / 4);

    gemm_tc_kernel<<<dim3(N / BN, M3 / BM, B), 256, GEMM_SMEM>>>(
        p_Whi, p_Wlo, p_ball, p_Xh, nullptr, p_pw, M3);

    dwconv_kernel<<<dim3(HW / 32, B * M3), dim3(32, 16)>>>(p_pw, p_dw);

    qk_tc_kernel<<<dim3(KSPLIT, B * HEADS), 192>>>(p_dw);

    softmax_kernel<<<B * HEADS, 256>>>(temp, d_l);

    av_tc_kernel<<<dim3(N / 512, B * HEADS), 192>>>(p_dw, p_avh);

    gemm_tc_kernel<<<dim3(N / BN, C / BM, B), 256, GEMM_SMEM>>>(
        p_Phi, p_Plo, prj_b, p_avh, outp, nullptr, C);
}

// round 15
// speedup vs baseline: 1.1746x; 1.1746x over previous
#include <cuda_runtime.h>
#include <cuda_bf16.h>
#include <cuda_fp16.h>
#include <math.h>
#include <stdint.h>

#define B 8
#define C 384
#define HW 128
#define N 16384
#define HEADS 8
#define HD 48
#define M3 1152
#define KSPLIT 32
#define EPSV 1e-12f

#define BM 64
#define BN 128
#define BK 32
#define APAD 40
#define BPAD 136

// ---------------- scratch ----------------
__device__ __align__(16) __half g_pw[(size_t)B * M3 * N];
__device__ __align__(16) __half g_dw[(size_t)B * M3 * N];
__device__ __align__(16) __half g_Xh[(size_t)B * C * N];
__device__ __align__(16) __half g_avh[(size_t)B * C * N];
__device__ __align__(16) __half g_Whi[M3 * C];
__device__ __align__(16) __half g_Phi[C * C];
__device__ __align__(16) __half g_Plo[C * C];
__device__ float g_ball[M3];
__device__ float g_DWall[M3 * 9];
__device__ float g_dwball[M3];
__device__ float g_norm2[B * 2 * C];
__device__ float g_dcp[B * C];
__device__ float g_attn_part[(size_t)B * HEADS * KSPLIT * HD * HD];
__device__ float g_attn[(size_t)B * HEADS * HD * HD];

__device__ __forceinline__ void split2h(float x, __half& h, __half& l) {
    h = __float2half(x);
    l = __float2half(x - __half2float(h));
}

// ---------------- PTX helpers ----------------
__device__ __forceinline__ void cpa16(uint32_t d, const void* s) {
    asm volatile("cp.async.cg.shared.global [%0], [%1], 16;\n" :: "r"(d), "l"(s));
}
__device__ __forceinline__ void cpa_commit() { asm volatile("cp.async.commit_group;\n"); }
__device__ __forceinline__ void cpa_wait2() { asm volatile("cp.async.wait_group 2;\n"); }
__device__ __forceinline__ void cpa_wait1() { asm volatile("cp.async.wait_group 1;\n"); }
__device__ __forceinline__ void cpa_wait0() { asm volatile("cp.async.wait_group 0;\n"); }

__device__ __forceinline__ void ldsm4(uint32_t* r, uint32_t addr) {
    asm volatile("ldmatrix.sync.aligned.m8n8.x4.shared.b16 {%0,%1,%2,%3}, [%4];"
                 : "=r"(r[0]), "=r"(r[1]), "=r"(r[2]), "=r"(r[3]) : "r"(addr));
}
__device__ __forceinline__ void ldsm2t(uint32_t* r, uint32_t addr) {
    asm volatile("ldmatrix.sync.aligned.m8n8.x2.trans.shared.b16 {%0,%1}, [%2];"
                 : "=r"(r[0]), "=r"(r[1]) : "r"(addr));
}
__device__ __forceinline__ void mma16816h(float* c, const uint32_t* a, const uint32_t* b) {
    asm volatile("mma.sync.aligned.m16n8k16.row.col.f32.f16.f16.f32 "
                 "{%0,%1,%2,%3}, {%4,%5,%6,%7}, {%8,%9}, {%0,%1,%2,%3};\n"
                 : "+f"(c[0]), "+f"(c[1]), "+f"(c[2]), "+f"(c[3])
                 : "r"(a[0]), "r"(a[1]), "r"(a[2]), "r"(a[3]), "r"(b[0]), "r"(b[1]));
}

// ---------------- weight packing ----------------
__global__ void pack_weights(
    const float* __restrict__ wq, const float* __restrict__ wqb,
    const float* __restrict__ wqd, const float* __restrict__ wqdb,
    const float* __restrict__ wk, const float* __restrict__ wkb,
    const float* __restrict__ wkd, const float* __restrict__ wkdb,
    const float* __restrict__ wv, const float* __restrict__ wvb,
    const float* __restrict__ wvd, const float* __restrict__ wvdb,
    const float* __restrict__ prj) {
    int i = blockIdx.x * blockDim.x + threadIdx.x;
    if (i < C * C) {
        g_Whi[i] = __float2half(wq[i]);
        g_Whi[C * C + i] = __float2half(wk[i]);
        g_Whi[2 * C * C + i] = __float2half(wv[i]);
        __half h, l;
        split2h(prj[i], h, l); g_Phi[i] = h; g_Plo[i] = l;
    }
    if (i < C * 9) {
        g_DWall[i] = wqd[i];
        g_DWall[C * 9 + i] = wkd[i];
        g_DWall[2 * C * 9 + i] = wvd[i];
    }
    if (i < C) {
        g_ball[i] = wqb[i];  g_ball[C + i] = wkb[i];  g_ball[2 * C + i] = wvb[i];
        g_dwball[i] = wqdb[i]; g_dwball[C + i] = wkdb[i]; g_dwball[2 * C + i] = wvdb[i];
    }
    if (i < B * 2 * C) g_norm2[i] = 0.f;
}

// ---------------- input -> fp16 ----------------
__global__ void split_kernel(const float* __restrict__ x, __half* __restrict__ xh, int n4) {
    int i = blockIdx.x * blockDim.x + threadIdx.x;
    if (i >= n4) return;
    float4 v = ((const float4*)x)[i];
    ((__half2*)xh)[i * 2] = __floats2half2_rn(v.x, v.y);
    ((__half2*)xh)[i * 2 + 1] = __floats2half2_rn(v.z, v.w);
}

// ---------------- degrade-class MLP ----------------
__global__ void dcp_kernel(const float* __restrict__ d_c,
                           const float* __restrict__ w1, const float* __restrict__ b1,
                           const float* __restrict__ w2, const float* __restrict__ b2) {
    __shared__ float hdn[48];
    int b = blockIdx.x;
    int t = threadIdx.x;
    if (t < 48) {
        float s = b1[t];
        #pragma unroll
        for (int i = 0; i < 3; i++) s += d_c[b * 3 + i] * w1[i * 48 + t];
        float x = s;
        float inner = 0.7978845608028654f * (x + 0.044715f * x * x * x);
        hdn[t] = 0.5f * x * (1.0f + tanhf(inner));
    }
    __syncthreads();
    float s = b2[t];
    #pragma unroll 8
    for (int j = 0; j < 48; j++) s += hdn[j] * w2[j * C + t];
    g_dcp[b * C + t] = s;
}

// ---------------- fp16 GEMM: 64x128 tile, 3-stage cp.async, templated weight-lo ----------------
#define A_STRIDE (BM * APAD)
#define B_STRIDE (BK * BPAD)
#define STG_ELEMS (2 * A_STRIDE + B_STRIDE)
#define OFF_ALO A_STRIDE
#define OFF_BH  (2 * A_STRIDE)
#define NSTG 3
#define GEMM_SMEM (NSTG * STG_ELEMS * 2)

template <bool LO>
__global__ void __launch_bounds__(256, 3) gemm_tc_kernel(
    const __half* __restrict__ Whi, const __half* __restrict__ Wlo,
    const float* __restrict__ bias,
    const __half* __restrict__ Xh,
    float* __restrict__ Yf, __half* __restrict__ Yh, int M) {
    extern __shared__ __half sm[];

    int b = blockIdx.z;
    const __half* XB = Xh + (size_t)b * C * N;
    int n0 = blockIdx.x * BN, m0 = blockIdx.y * BM;
    int t = threadIdx.x, lane = t & 31, w = t >> 5;
    int wm = (w >> 2) * 32, wn = (w & 3) * 32;

    int aRow = t >> 2, aSeg = (t & 3) * 8;
    int bRow0 = (2 * t) >> 4, bSeg0 = ((2 * t) & 15) * 8;
    int bRow1 = (2 * t + 1) >> 4, bSeg1 = ((2 * t + 1) & 15) * 8;

    float acc[2][4][4];
    #pragma unroll
    for (int mi = 0; mi < 2; mi++)
        #pragma unroll
        for (int ni = 0; ni < 4; ni++)
            #pragma unroll
            for (int r = 0; r < 4; r++) acc[mi][ni][r] = 0.f;

    auto issue = [&](int k0, int st) {
        __half* base = sm + st * STG_ELEMS;
        cpa16((uint32_t)__cvta_generic_to_shared(base + aRow * APAD + aSeg),
              Whi + (size_t)(m0 + aRow) * C + k0 + aSeg);
        if (LO)
            cpa16((uint32_t)__cvta_generic_to_shared(base + OFF_ALO + aRow * APAD + aSeg),
                  Wlo + (size_t)(m0 + aRow) * C + k0 + aSeg);
        cpa16((uint32_t)__cvta_generic_to_shared(base + OFF_BH + bRow0 * BPAD + bSeg0),
              XB + (size_t)(k0 + bRow0) * N + n0 + bSeg0);
        cpa16((uint32_t)__cvta_generic_to_shared(base + OFF_BH + bRow1 * BPAD + bSeg1),
              XB + (size_t)(k0 + bRow1) * N + n0 + bSeg1);
        cpa_commit();
    };

    const int NIT = C / BK;
    issue(0, 0);
    issue(BK, 1);
    for (int it = 0; it < NIT; it++) {
        if (it + 2 < NIT) { issue((it + 2) * BK, (it + 2) % NSTG); cpa_wait2(); }
        else if (it + 1 < NIT) cpa_wait1();
        else cpa_wait0();
        __syncthreads();
        __half* base = sm + (it % NSTG) * STG_ELEMS;
        __half* ah_s = base;
        __half* al_s = base + OFF_ALO;
        __half* bh_s = base + OFF_BH;
        #pragma unroll
        for (int kk = 0; kk < BK; kk += 16) {
            uint32_t bhf[4][2];
            #pragma unroll
            for (int ni = 0; ni < 4; ni++)
                ldsm2t(bhf[ni], (uint32_t)__cvta_generic_to_shared(
                    bh_s + (kk + (lane & 15)) * BPAD + wn + ni * 8));
            #pragma unroll
            for (int mi = 0; mi < 2; mi++) {
                uint32_t ahf[4], alf[4];
                ldsm4(ahf, (uint32_t)__cvta_generic_to_shared(
                    ah_s + (wm + mi * 16 + (lane & 15)) * APAD + kk + ((lane >> 4) << 3)));
                if (LO)
                    ldsm4(alf, (uint32_t)__cvta_generic_to_shared(
                        al_s + (wm + mi * 16 + (lane & 15)) * APAD + kk + ((lane >> 4) << 3)));
                #pragma unroll
                for (int ni = 0; ni < 4; ni++) {
                    mma16816h(acc[mi][ni], ahf, bhf[ni]);
                    if (LO) mma16816h(acc[mi][ni], alf, bhf[ni]);
                }
            }
        }
        __syncthreads();
    }

    int r = lane >> 2;
    #pragma unroll
    for (int mi = 0; mi < 2; mi++) {
        int m1 = m0 + wm + mi * 16 + r;
        int m2 = m1 + 8;
        float b1 = bias[m1], b2 = bias[m2];
        #pragma unroll
        for (int ni = 0; ni < 4; ni++) {
            int col = n0 + wn + ni * 8 + (lane & 3) * 2;
            if (Yh) {
                __half* Yb = Yh + (size_t)b * (size_t)M * N;
                *(__half2*)&Yb[(size_t)m1 * N + col] =
                    __floats2half2_rn(acc[mi][ni][0] + b1, acc[mi][ni][1] + b1);
                *(__half2*)&Yb[(size_t)m2 * N + col] =
                    __floats2half2_rn(acc[mi][ni][2] + b2, acc[mi][ni][3] + b2);
            } else {
                float* Yb = Yf + (size_t)b * (size_t)M * N;
                *(float2*)&Yb[(size_t)m1 * N + col] =
                    make_float2(acc[mi][ni][0] + b1, acc[mi][ni][1] + b1);
                *(float2*)&Yb[(size_t)m2 * N + col] =
                    make_float2(acc[mi][ni][2] + b2, acc[mi][ni][3] + b2);
            }
        }
    }
}

// ---------------- depthwise 3x3: 16-row tiles, fp16 in/out, fused sumsq ----------------
__global__ void __launch_bounds__(256) dwconv_kernel(const __half* __restrict__ in,
                                                     __half* __restrict__ out) {
    __shared__ float s[18][132];
    __shared__ float red[8];
    int plane = blockIdx.y;
    int ch = plane % M3;
    int b = plane / M3;
    int y0 = blockIdx.x * 16;
    const __half* ip = in + (size_t)plane * N;
    __half* op = out + (size_t)plane * N;
    int tx = threadIdx.x, ty = threadIdx.y;
    int t = ty * 32 + tx;

    for (int i = t; i < 288; i += 256) {
        int r = i >> 4, c8 = i & 15;
        int gy = y0 - 1 + r;
        uint4 raw = make_uint4(0, 0, 0, 0);
        if (gy >= 0 && gy < HW) raw = *(const uint4*)(ip + gy * HW + c8 * 8);
        const __half2* hp = (const __half2*)&raw;
        #pragma unroll
        for (int k2 = 0; k2 < 4; k2++) {
            float2 f = __half22float2(hp[k2]);
            s[r][1 + c8 * 8 + k2 * 2] = f.x;
            s[r][1 + c8 * 8 + k2 * 2 + 1] = f.y;
        }
        if (c8 == 0) s[r][0] = 0.f;
        if (c8 == 15) s[r][129] = 0.f;
    }
    __syncthreads();

    float wgt[9];
    #pragma unroll
    for (int i = 0; i < 9; i++) wgt[i] = g_DWall[ch * 9 + i];
    float bsv = g_dwball[ch];

    float o[2][4];
    #pragma unroll
    for (int g = 0; g < 2; g++)
        #pragma unroll
        for (int j = 0; j < 4; j++) o[g][j] = bsv;
    #pragma unroll
    for (int rr = 0; rr < 3; rr++) {
        float w0 = wgt[rr * 3 + 0], w1 = wgt[rr * 3 + 1], w2 = wgt[rr * 3 + 2];
        #pragma unroll
        for (int g = 0; g < 2; g++) {
            float v[6];
            #pragma unroll
            for (int j = 0; j < 6; j++) v[j] = s[ty + g * 8 + rr][tx * 4 + j];
            #pragma unroll
            for (int j = 0; j < 4; j++)
                o[g][j] += w0 * v[j] + w1 * v[j + 1] + w2 * v[j + 2];
        }
    }
    float ss = 0.f;
    #pragma unroll
    for (int g = 0; g < 2; g++) {
        __half2 h0 = __floats2half2_rn(o[g][0], o[g][1]);
        __half2 h1 = __floats2half2_rn(o[g][2], o[g][3]);
        __half* dst = op + (y0 + ty + g * 8) * HW + tx * 4;
        *(__half2*)dst = h0;
        *(__half2*)(dst + 2) = h1;
        float2 f0 = __half22float2(h0), f1 = __half22float2(h1);
        ss += f0.x * f0.x + f0.y * f0.y + f1.x * f1.x + f1.y * f1.y;
    }

    if (ch < 2 * C) {
        #pragma unroll
        for (int off = 16; off > 0; off >>= 1)
            ss += __shfl_down_sync(0xffffffffu, ss, off);
        int wid = t >> 5;
        if ((t & 31) == 0) red[wid] = ss;
        __syncthreads();
        if (t == 0) {
            float tot = 0.f;
            #pragma unroll
            for (int i = 0; i < 8; i++) tot += red[i];
            atomicAdd(&g_norm2[b * 768 + ch], tot);
        }
    }
}

// ---------------- QK^T: single fp16 mma, split-K over tokens ----------------
#define QNT 64
#define QP 72
#define KP 56
__global__ void __launch_bounds__(192) qk_tc_kernel(const __half* __restrict__ dwbuf) {
    __shared__ __half qs[HD * QP];
    __shared__ __half ks[QNT * KP];
    __shared__ float redbuf[3 * 6 * 128];

    int bh = blockIdx.y;
    int b = bh >> 3, h = bh & 7;
    const __half* qp = dwbuf + ((size_t)b * M3 + h * HD) * N;
    const __half* kp = dwbuf + ((size_t)b * M3 + C + h * HD) * N;
    int n0 = blockIdx.x * (N / KSPLIT);
    int t = threadIdx.x, lane = t & 31, w = t >> 5;
    int mi = w % 3, kh = w / 3;

    float acc[6][4];
    #pragma unroll
    for (int ni = 0; ni < 6; ni++)
        #pragma unroll
        for (int r = 0; r < 4; r++) acc[ni][r] = 0.f;

    for (int s = 0; s < (N / KSPLIT) / QNT; s++) {
        int off = n0 + s * QNT;
        for (int i = t; i < HD * 8; i += 192) {
            int c = i >> 3, chk = (i & 7) * 8;
            *(uint4*)&qs[c * QP + chk] = *(const uint4*)(qp + (size_t)c * N + off + chk);
        }
        for (int i = t; i < HD * 32; i += 192) {
            int d = i >> 5, n2 = (i & 31) * 2;
            __half2 v = *(const __half2*)(kp + (size_t)d * N + off + n2);
            ks[(n2 + 0) * KP + d] = __low2half(v);
            ks[(n2 + 1) * KP + d] = __high2half(v);
        }
        __syncthreads();
        #pragma unroll
        for (int kk2 = 0; kk2 < 2; kk2++) {
            int kk = kh * 32 + kk2 * 16;
            uint32_t ahf[4];
            ldsm4(ahf, (uint32_t)__cvta_generic_to_shared(
                &qs[(mi * 16 + (lane & 15)) * QP + kk + ((lane >> 4) << 3)]));
            #pragma unroll
            for (int ni = 0; ni < 6; ni++) {
                uint32_t bhf[2];
                ldsm2t(bhf, (uint32_t)__cvta_generic_to_shared(
                    &ks[(kk + (lane & 15)) * KP + ni * 8]));
                mma16816h(acc[ni], ahf, bhf);
            }
        }
        __syncthreads();
    }

    if (kh == 1) {
        #pragma unroll
        for (int ni = 0; ni < 6; ni++)
            #pragma unroll
            for (int r = 0; r < 4; r++)
                redbuf[(mi * 6 + ni) * 128 + lane * 4 + r] = acc[ni][r];
    }
    __syncthreads();
    if (kh == 0) {
        float* outp = g_attn_part + ((size_t)bh * KSPLIT + blockIdx.x) * (HD * HD);
        #pragma unroll
        for (int ni = 0; ni < 6; ni++) {
            #pragma unroll
            for (int r = 0; r < 4; r++)
                acc[ni][r] += redbuf[(mi * 6 + ni) * 128 + lane * 4 + r];
            int c0 = mi * 16 + (lane >> 2);
            int d0 = ni * 8 + (lane & 3) * 2;
            outp[c0 * HD + d0]       = acc[ni][0];
            outp[c0 * HD + d0 + 1]   = acc[ni][1];
            outp[(c0 + 8) * HD + d0]     = acc[ni][2];
            outp[(c0 + 8) * HD + d0 + 1] = acc[ni][3];
        }
    }
}

// ---------------- combine, modulate, softmax ----------------
__global__ void softmax_kernel(const float* __restrict__ temp, const float* __restrict__ d_l) {
    __shared__ float S[HD * HD];
    int bh = blockIdx.x;
    int b = bh >> 3, h = bh & 7;
    int t = threadIdx.x;
    float tscale = temp[h] * d_l[b];
    for (int idx = t; idx < HD * HD; idx += 256) {
        const float* pp = g_attn_part + (size_t)bh * KSPLIT * (HD * HD) + idx;
        float s = 0.f;
        #pragma unroll
        for (int sp = 0; sp < KSPLIT; sp++) s += pp[(size_t)sp * (HD * HD)];
        int c = idx / HD, d = idx % HD;
        float nq = fmaxf(sqrtf(g_norm2[b * 768 + h * HD + c]), EPSV);
        float nk = fmaxf(sqrtf(g_norm2[b * 768 + C + h * HD + d]), EPSV);
        S[idx] = s / (nq * nk) * tscale * g_dcp[b * C + h * HD + c];
    }
    __syncthreads();
    if (t < HD) {
        float mx = -1e30f;
        for (int d = 0; d < HD; d++) mx = fmaxf(mx, S[t * HD + d]);
        float sum = 0.f;
        for (int d = 0; d < HD; d++) sum += expf(S[t * HD + d] - mx);
        float inv = 1.f / sum;
        for (int d = 0; d < HD; d++)
            g_attn[(size_t)bh * (HD * HD) + t * HD + d] = expf(S[t * HD + d] - mx) * inv;
    }
}

// ---------------- attn @ v: tensor-core (M=48, K=48), fp16 in/out ----------------
#define AVP 136
__global__ void __launch_bounds__(192) av_tc_kernel(const __half* __restrict__ dwbuf,
                                                    __half* __restrict__ oh) {
    __shared__ __half As[HD * 56];
    __shared__ __half vs[HD * AVP];
    int bh = blockIdx.y;
    int b = bh >> 3, h = bh & 7;
    const __half* vp = dwbuf + ((size_t)b * M3 + 2 * C + h * HD) * N;
    __half* op = oh + ((size_t)b * C + h * HD) * N;
    int t = threadIdx.x, lane = t & 31, w = t >> 5;
    int mi = w % 3, nh = w / 3;

    const float* ap = g_attn + (size_t)bh * (HD * HD);
    for (int i = t; i < HD * HD; i += 192) {
        int c = i / HD, d = i % HD;
        As[c * 56 + d] = __float2half(ap[i]);
    }
    __syncthreads();

    int n0 = blockIdx.x * 512;
    for (int chunk = 0; chunk < 4; chunk++) {
        int off = n0 + chunk * 128;
        for (int i = t; i < HD * 16; i += 192) {
            int d = i >> 4, c16 = (i & 15) * 8;
            *(uint4*)&vs[d * AVP + c16] = *(const uint4*)(vp + (size_t)d * N + off + c16);
        }
        __syncthreads();

        float acc[8][4];
        #pragma unroll
        for (int ni = 0; ni < 8; ni++)
            #pragma unroll
            for (int r = 0; r < 4; r++) acc[ni][r] = 0.f;

        #pragma unroll
        for (int kk2 = 0; kk2 < 3; kk2++) {
            int kk = kk2 * 16;
            uint32_t af[4];
            ldsm4(af, (uint32_t)__cvta_generic_to_shared(
                &As[(mi * 16 + (lane & 15)) * 56 + kk + ((lane >> 4) << 3)]));
            #pragma unroll
            for (int ni = 0; ni < 8; ni++) {
                uint32_t bf[2];
                ldsm2t(bf, (uint32_t)__cvta_generic_to_shared(
                    &vs[(kk + (lane & 15)) * AVP + nh * 64 + ni * 8]));
                mma16816h(acc[ni], af, bf);
            }
        }

        int r = lane >> 2;
        int c1 = mi * 16 + r, c2 = c1 + 8;
        #pragma unroll
        for (int ni = 0; ni < 8; ni++) {
            int col = off + nh * 64 + ni * 8 + (lane & 3) * 2;
            *(__half2*)&op[(size_t)c1 * N + col] = __floats2half2_rn(acc[ni][0], acc[ni][1]);
            *(__half2*)&op[(size_t)c2 * N + col] = __floats2half2_rn(acc[ni][2], acc[ni][3]);
        }
        __syncthreads();
    }
}

// ---------------- launch ----------------
extern "C" void kernel_launch(void* const* d_in, const int* in_sizes, int n_in,
                              void* d_out, int out_size) {
    const float* inputs  = (const float*)d_in[0];
    const float* d_c     = (const float*)d_in[1];
    const float* d_l     = (const float*)d_in[2];
    const float* temp    = (const float*)d_in[3];
    const float* prj_w   = (const float*)d_in[4];
    const float* prj_b   = (const float*)d_in[5];
    const float* dp_w1   = (const float*)d_in[6];
    const float* dp_b1   = (const float*)d_in[7];
    const float* dp_w2   = (const float*)d_in[8];
    const float* dp_b2   = (const float*)d_in[9];
    const float* wq_pw   = (const float*)d_in[10];
    const float* wq_pw_b = (const float*)d_in[11];
    const float* wq_dw   = (const float*)d_in[12];
    const float* wq_dw_b = (const float*)d_in[13];
    const float* wk_pw   = (const float*)d_in[14];
    const float* wk_pw_b = (const float*)d_in[15];
    const float* wk_dw   = (const float*)d_in[16];
    const float* wk_dw_b = (const float*)d_in[17];
    const float* wv_pw   = (const float*)d_in[18];
    const float* wv_pw_b = (const float*)d_in[19];
    const float* wv_dw   = (const float*)d_in[20];
    const float* wv_dw_b = (const float*)d_in[21];
    float* outp = (float*)d_out;

    __half *p_Whi, *p_Phi, *p_Plo, *p_Xh, *p_avh, *p_pw, *p_dw;
    float *p_ball;
    cudaGetSymbolAddress((void**)&p_Whi, g_Whi);
    cudaGetSymbolAddress((void**)&p_Phi, g_Phi);
    cudaGetSymbolAddress((void**)&p_Plo, g_Plo);
    cudaGetSymbolAddress((void**)&p_Xh, g_Xh);
    cudaGetSymbolAddress((void**)&p_avh, g_avh);
    cudaGetSymbolAddress((void**)&p_ball, g_ball);
    cudaGetSymbolAddress((void**)&p_pw, g_pw);
    cudaGetSymbolAddress((void**)&p_dw, g_dw);

    cudaFuncSetAttribute(gemm_tc_kernel<false>,
                         cudaFuncAttributeMaxDynamicSharedMemorySize, GEMM_SMEM);
    cudaFuncSetAttribute(gemm_tc_kernel<true>,
                         cudaFuncAttributeMaxDynamicSharedMemorySize, GEMM_SMEM);

    pack_weights<<<(C * C + 255) / 256, 256>>>(
        wq_pw, wq_pw_b, wq_dw, wq_dw_b,
        wk_pw, wk_pw_b, wk_dw, wk_dw_b,
        wv_pw, wv_pw_b, wv_dw, wv_dw_b, prj_w);

    dcp_kernel<<<B, C>>>(d_c, dp_w1, dp_b1, dp_w2, dp_b2);

    split_kernel<<<(B * C * N / 4 + 255) / 256, 256>>>(inputs, p_Xh, B * C * N / 4);

    // QKV GEMM: single-product weights -> fp16 output
    gemm_tc_kernel<false><<<dim3(N / BN, M3 / BM, B), 256, GEMM_SMEM>>>(
        p_Whi, nullptr, p_ball, p_Xh, nullptr, p_pw, M3);

    dwconv_kernel<<<dim3(HW / 16, B * M3), dim3(32, 8)>>>(p_pw, p_dw);

    qk_tc_kernel<<<dim3(KSPLIT, B * HEADS), 192>>>(p_dw);

    softmax_kernel<<<B * HEADS, 256>>>(temp, d_l);

    av_tc_kernel<<<dim3(N / 512, B * HEADS), 192>>>(p_dw, p_avh);

    // projection GEMM: 2-product weights -> fp32 output
    gemm_tc_kernel<true><<<dim3(N / BN, C / BM, B), 256, GEMM_SMEM>>>(
        p_Phi, p_Plo, prj_b, p_avh, outp, nullptr, C);
}

// round 16
// speedup vs baseline: 1.2465x; 1.0612x over previous
#include <cuda_runtime.h>
#include <cuda_bf16.h>
#include <cuda_fp16.h>
#include <math.h>
#include <stdint.h>

#define B 8
#define C 384
#define HW 128
#define N 16384
#define HEADS 8
#define HD 48
#define M3 1152
#define KSPLIT 32
#define EPSV 1e-12f

#define BM 64
#define BN 128
#define BK 32
#define APAD 40
#define BPAD 136

// ---------------- scratch ----------------
__device__ __align__(16) __half g_pw[(size_t)B * M3 * N];
__device__ __align__(16) __half g_dw[(size_t)B * M3 * N];
__device__ __align__(16) __half g_Xh[(size_t)B * C * N];
__device__ __align__(16) __half g_avh[(size_t)B * C * N];
__device__ __align__(16) __half g_Whi[M3 * C];
__device__ __align__(16) __half g_Phi[C * C];
__device__ float g_ball[M3];
__device__ float g_DWall[M3 * 9];
__device__ float g_dwball[M3];
__device__ float g_norm2[B * 2 * C];
__device__ float g_dcp[B * C];
__device__ float g_attn_part[(size_t)B * HEADS * KSPLIT * HD * HD];
__device__ float g_attn[(size_t)B * HEADS * HD * HD];

// ---------------- PTX helpers ----------------
__device__ __forceinline__ void cpa16(uint32_t d, const void* s) {
    asm volatile("cp.async.cg.shared.global [%0], [%1], 16;\n" :: "r"(d), "l"(s));
}
__device__ __forceinline__ void cpa_commit() { asm volatile("cp.async.commit_group;\n"); }
__device__ __forceinline__ void cpa_wait2() { asm volatile("cp.async.wait_group 2;\n"); }
__device__ __forceinline__ void cpa_wait1() { asm volatile("cp.async.wait_group 1;\n"); }
__device__ __forceinline__ void cpa_wait0() { asm volatile("cp.async.wait_group 0;\n"); }

__device__ __forceinline__ void ldsm4(uint32_t* r, uint32_t addr) {
    asm volatile("ldmatrix.sync.aligned.m8n8.x4.shared.b16 {%0,%1,%2,%3}, [%4];"
                 : "=r"(r[0]), "=r"(r[1]), "=r"(r[2]), "=r"(r[3]) : "r"(addr));
}
__device__ __forceinline__ void ldsm2t(uint32_t* r, uint32_t addr) {
    asm volatile("ldmatrix.sync.aligned.m8n8.x2.trans.shared.b16 {%0,%1}, [%2];"
                 : "=r"(r[0]), "=r"(r[1]) : "r"(addr));
}
__device__ __forceinline__ void mma16816h(float* c, const uint32_t* a, const uint32_t* b) {
    asm volatile("mma.sync.aligned.m16n8k16.row.col.f32.f16.f16.f32 "
                 "{%0,%1,%2,%3}, {%4,%5,%6,%7}, {%8,%9}, {%0,%1,%2,%3};\n"
                 : "+f"(c[0]), "+f"(c[1]), "+f"(c[2]), "+f"(c[3])
                 : "r"(a[0]), "r"(a[1]), "r"(a[2]), "r"(a[3]), "r"(b[0]), "r"(b[1]));
}

// ---------------- weight packing ----------------
__global__ void pack_weights(
    const float* __restrict__ wq, const float* __restrict__ wqb,
    const float* __restrict__ wqd, const float* __restrict__ wqdb,
    const float* __restrict__ wk, const float* __restrict__ wkb,
    const float* __restrict__ wkd, const float* __restrict__ wkdb,
    const float* __restrict__ wv, const float* __restrict__ wvb,
    const float* __restrict__ wvd, const float* __restrict__ wvdb,
    const float* __restrict__ prj) {
    int i = blockIdx.x * blockDim.x + threadIdx.x;
    if (i < C * C) {
        g_Whi[i] = __float2half(wq[i]);
        g_Whi[C * C + i] = __float2half(wk[i]);
        g_Whi[2 * C * C + i] = __float2half(wv[i]);
        g_Phi[i] = __float2half(prj[i]);
    }
    if (i < C * 9) {
        g_DWall[i] = wqd[i];
        g_DWall[C * 9 + i] = wkd[i];
        g_DWall[2 * C * 9 + i] = wvd[i];
    }
    if (i < C) {
        g_ball[i] = wqb[i];  g_ball[C + i] = wkb[i];  g_ball[2 * C + i] = wvb[i];
        g_dwball[i] = wqdb[i]; g_dwball[C + i] = wkdb[i]; g_dwball[2 * C + i] = wvdb[i];
    }
    if (i < B * 2 * C) g_norm2[i] = 0.f;
}

// ---------------- input -> fp16 ----------------
__global__ void split_kernel(const float* __restrict__ x, __half* __restrict__ xh, int n4) {
    int i = blockIdx.x * blockDim.x + threadIdx.x;
    if (i >= n4) return;
    float4 v = ((const float4*)x)[i];
    ((__half2*)xh)[i * 2] = __floats2half2_rn(v.x, v.y);
    ((__half2*)xh)[i * 2 + 1] = __floats2half2_rn(v.z, v.w);
}

// ---------------- degrade-class MLP ----------------
__global__ void dcp_kernel(const float* __restrict__ d_c,
                           const float* __restrict__ w1, const float* __restrict__ b1,
                           const float* __restrict__ w2, const float* __restrict__ b2) {
    __shared__ float hdn[48];
    int b = blockIdx.x;
    int t = threadIdx.x;
    if (t < 48) {
        float s = b1[t];
        #pragma unroll
        for (int i = 0; i < 3; i++) s += d_c[b * 3 + i] * w1[i * 48 + t];
        float x = s;
        float inner = 0.7978845608028654f * (x + 0.044715f * x * x * x);
        hdn[t] = 0.5f * x * (1.0f + tanhf(inner));
    }
    __syncthreads();
    float s = b2[t];
    #pragma unroll 8
    for (int j = 0; j < 48; j++) s += hdn[j] * w2[j * C + t];
    g_dcp[b * C + t] = s;
}

// ---------------- fp16 GEMM: 64x128 tile, 3-stage cp.async, single-product ----------------
#define A_STRIDE (BM * APAD)
#define B_STRIDE (BK * BPAD)
#define STG_ELEMS (A_STRIDE + B_STRIDE)
#define OFF_BH  A_STRIDE
#define NSTG 3
#define GEMM_SMEM (NSTG * STG_ELEMS * 2)

__global__ void __launch_bounds__(256, 3) gemm_tc_kernel(
    const __half* __restrict__ Wh,
    const float* __restrict__ bias,
    const __half* __restrict__ Xh,
    float* __restrict__ Yf, __half* __restrict__ Yh, int M) {
    extern __shared__ __half sm[];

    int b = blockIdx.z;
    const __half* XB = Xh + (size_t)b * C * N;
    int n0 = blockIdx.x * BN, m0 = blockIdx.y * BM;
    int t = threadIdx.x, lane = t & 31, w = t >> 5;
    int wm = (w >> 2) * 32, wn = (w & 3) * 32;

    int aRow = t >> 2, aSeg = (t & 3) * 8;
    int bRow0 = (2 * t) >> 4, bSeg0 = ((2 * t) & 15) * 8;
    int bRow1 = (2 * t + 1) >> 4, bSeg1 = ((2 * t + 1) & 15) * 8;

    float acc[2][4][4];
    #pragma unroll
    for (int mi = 0; mi < 2; mi++)
        #pragma unroll
        for (int ni = 0; ni < 4; ni++)
            #pragma unroll
            for (int r = 0; r < 4; r++) acc[mi][ni][r] = 0.f;

    auto issue = [&](int k0, int st) {
        __half* base = sm + st * STG_ELEMS;
        cpa16((uint32_t)__cvta_generic_to_shared(base + aRow * APAD + aSeg),
              Wh + (size_t)(m0 + aRow) * C + k0 + aSeg);
        cpa16((uint32_t)__cvta_generic_to_shared(base + OFF_BH + bRow0 * BPAD + bSeg0),
              XB + (size_t)(k0 + bRow0) * N + n0 + bSeg0);
        cpa16((uint32_t)__cvta_generic_to_shared(base + OFF_BH + bRow1 * BPAD + bSeg1),
              XB + (size_t)(k0 + bRow1) * N + n0 + bSeg1);
        cpa_commit();
    };

    const int NIT = C / BK;
    issue(0, 0);
    issue(BK, 1);
    for (int it = 0; it < NIT; it++) {
        if (it + 2 < NIT) { issue((it + 2) * BK, (it + 2) % NSTG); cpa_wait2(); }
        else if (it + 1 < NIT) cpa_wait1();
        else cpa_wait0();
        __syncthreads();
        __half* base = sm + (it % NSTG) * STG_ELEMS;
        __half* ah_s = base;
        __half* bh_s = base + OFF_BH;
        #pragma unroll
        for (int kk = 0; kk < BK; kk += 16) {
            uint32_t bhf[4][2];
            #pragma unroll
            for (int ni = 0; ni < 4; ni++)
                ldsm2t(bhf[ni], (uint32_t)__cvta_generic_to_shared(
                    bh_s + (kk + (lane & 15)) * BPAD + wn + ni * 8));
            #pragma unroll
            for (int mi = 0; mi < 2; mi++) {
                uint32_t ahf[4];
                ldsm4(ahf, (uint32_t)__cvta_generic_to_shared(
                    ah_s + (wm + mi * 16 + (lane & 15)) * APAD + kk + ((lane >> 4) << 3)));
                #pragma unroll
                for (int ni = 0; ni < 4; ni++)
                    mma16816h(acc[mi][ni], ahf, bhf[ni]);
            }
        }
        __syncthreads();
    }

    int r = lane >> 2;
    #pragma unroll
    for (int mi = 0; mi < 2; mi++) {
        int m1 = m0 + wm + mi * 16 + r;
        int m2 = m1 + 8;
        float b1 = bias[m1], b2 = bias[m2];
        #pragma unroll
        for (int ni = 0; ni < 4; ni++) {
            int col = n0 + wn + ni * 8 + (lane & 3) * 2;
            if (Yh) {
                __half* Yb = Yh + (size_t)b * (size_t)M * N;
                *(__half2*)&Yb[(size_t)m1 * N + col] =
                    __floats2half2_rn(acc[mi][ni][0] + b1, acc[mi][ni][1] + b1);
                *(__half2*)&Yb[(size_t)m2 * N + col] =
                    __floats2half2_rn(acc[mi][ni][2] + b2, acc[mi][ni][3] + b2);
            } else {
                float* Yb = Yf + (size_t)b * (size_t)M * N;
                *(float2*)&Yb[(size_t)m1 * N + col] =
                    make_float2(acc[mi][ni][0] + b1, acc[mi][ni][1] + b1);
                *(float2*)&Yb[(size_t)m2 * N + col] =
                    make_float2(acc[mi][ni][2] + b2, acc[mi][ni][3] + b2);
            }
        }
    }
}

// ---------------- depthwise 3x3: 16-row tiles, fp16 in/out, fused sumsq ----------------
__global__ void __launch_bounds__(256) dwconv_kernel(const __half* __restrict__ in,
                                                     __half* __restrict__ out) {
    __shared__ float s[18][132];
    __shared__ float red[8];
    int plane = blockIdx.y;
    int ch = plane % M3;
    int b = plane / M3;
    int y0 = blockIdx.x * 16;
    const __half* ip = in + (size_t)plane * N;
    __half* op = out + (size_t)plane * N;
    int tx = threadIdx.x, ty = threadIdx.y;
    int t = ty * 32 + tx;

    for (int i = t; i < 288; i += 256) {
        int r = i >> 4, c8 = i & 15;
        int gy = y0 - 1 + r;
        uint4 raw = make_uint4(0, 0, 0, 0);
        if (gy >= 0 && gy < HW) raw = *(const uint4*)(ip + gy * HW + c8 * 8);
        const __half2* hp = (const __half2*)&raw;
        #pragma unroll
        for (int k2 = 0; k2 < 4; k2++) {
            float2 f = __half22float2(hp[k2]);
            s[r][1 + c8 * 8 + k2 * 2] = f.x;
            s[r][1 + c8 * 8 + k2 * 2 + 1] = f.y;
        }
        if (c8 == 0) s[r][0] = 0.f;
        if (c8 == 15) s[r][129] = 0.f;
    }
    __syncthreads();

    float wgt[9];
    #pragma unroll
    for (int i = 0; i < 9; i++) wgt[i] = g_DWall[ch * 9 + i];
    float bsv = g_dwball[ch];

    float o[2][4];
    #pragma unroll
    for (int g = 0; g < 2; g++)
        #pragma unroll
        for (int j = 0; j < 4; j++) o[g][j] = bsv;
    #pragma unroll
    for (int rr = 0; rr < 3; rr++) {
        float w0 = wgt[rr * 3 + 0], w1 = wgt[rr * 3 + 1], w2 = wgt[rr * 3 + 2];
        #pragma unroll
        for (int g = 0; g < 2; g++) {
            float v[6];
            #pragma unroll
            for (int j = 0; j < 6; j++) v[j] = s[ty + g * 8 + rr][tx * 4 + j];
            #pragma unroll
            for (int j = 0; j < 4; j++)
                o[g][j] += w0 * v[j] + w1 * v[j + 1] + w2 * v[j + 2];
        }
    }
    float ss = 0.f;
    #pragma unroll
    for (int g = 0; g < 2; g++) {
        __half2 h0 = __floats2half2_rn(o[g][0], o[g][1]);
        __half2 h1 = __floats2half2_rn(o[g][2], o[g][3]);
        __half* dst = op + (y0 + ty + g * 8) * HW + tx * 4;
        *(__half2*)dst = h0;
        *(__half2*)(dst + 2) = h1;
        float2 f0 = __half22float2(h0), f1 = __half22float2(h1);
        ss += f0.x * f0.x + f0.y * f0.y + f1.x * f1.x + f1.y * f1.y;
    }

    if (ch < 2 * C) {
        #pragma unroll
        for (int off = 16; off > 0; off >>= 1)
            ss += __shfl_down_sync(0xffffffffu, ss, off);
        int wid = t >> 5;
        if ((t & 31) == 0) red[wid] = ss;
        __syncthreads();
        if (t == 0) {
            float tot = 0.f;
            #pragma unroll
            for (int i = 0; i < 8; i++) tot += red[i];
            atomicAdd(&g_norm2[b * 768 + ch], tot);
        }
    }
}

// ---------------- QK^T: single fp16 mma, split-K over tokens ----------------
#define QNT 64
#define QP 72
#define KP 56
__global__ void __launch_bounds__(192) qk_tc_kernel(const __half* __restrict__ dwbuf) {
    __shared__ __half qs[HD * QP];
    __shared__ __half ks[QNT * KP];
    __shared__ float redbuf[3 * 6 * 128];

    int bh = blockIdx.y;
    int b = bh >> 3, h = bh & 7;
    const __half* qp = dwbuf + ((size_t)b * M3 + h * HD) * N;
    const __half* kp = dwbuf + ((size_t)b * M3 + C + h * HD) * N;
    int n0 = blockIdx.x * (N / KSPLIT);
    int t = threadIdx.x, lane = t & 31, w = t >> 5;
    int mi = w % 3, kh = w / 3;

    float acc[6][4];
    #pragma unroll
    for (int ni = 0; ni < 6; ni++)
        #pragma unroll
        for (int r = 0; r < 4; r++) acc[ni][r] = 0.f;

    for (int s = 0; s < (N / KSPLIT) / QNT; s++) {
        int off = n0 + s * QNT;
        for (int i = t; i < HD * 8; i += 192) {
            int c = i >> 3, chk = (i & 7) * 8;
            *(uint4*)&qs[c * QP + chk] = *(const uint4*)(qp + (size_t)c * N + off + chk);
        }
        for (int i = t; i < HD * 32; i += 192) {
            int d = i >> 5, n2 = (i & 31) * 2;
            __half2 v = *(const __half2*)(kp + (size_t)d * N + off + n2);
            ks[(n2 + 0) * KP + d] = __low2half(v);
            ks[(n2 + 1) * KP + d] = __high2half(v);
        }
        __syncthreads();
        #pragma unroll
        for (int kk2 = 0; kk2 < 2; kk2++) {
            int kk = kh * 32 + kk2 * 16;
            uint32_t ahf[4];
            ldsm4(ahf, (uint32_t)__cvta_generic_to_shared(
                &qs[(mi * 16 + (lane & 15)) * QP + kk + ((lane >> 4) << 3)]));
            #pragma unroll
            for (int ni = 0; ni < 6; ni++) {
                uint32_t bhf[2];
                ldsm2t(bhf, (uint32_t)__cvta_generic_to_shared(
                    &ks[(kk + (lane & 15)) * KP + ni * 8]));
                mma16816h(acc[ni], ahf, bhf);
            }
        }
        __syncthreads();
    }

    if (kh == 1) {
        #pragma unroll
        for (int ni = 0; ni < 6; ni++)
            #pragma unroll
            for (int r = 0; r < 4; r++)
                redbuf[(mi * 6 + ni) * 128 + lane * 4 + r] = acc[ni][r];
    }
    __syncthreads();
    if (kh == 0) {
        float* outp = g_attn_part + ((size_t)bh * KSPLIT + blockIdx.x) * (HD * HD);
        #pragma unroll
        for (int ni = 0; ni < 6; ni++) {
            #pragma unroll
            for (int r = 0; r < 4; r++)
                acc[ni][r] += redbuf[(mi * 6 + ni) * 128 + lane * 4 + r];
            int c0 = mi * 16 + (lane >> 2);
            int d0 = ni * 8 + (lane & 3) * 2;
            outp[c0 * HD + d0]       = acc[ni][0];
            outp[c0 * HD + d0 + 1]   = acc[ni][1];
            outp[(c0 + 8) * HD + d0]     = acc[ni][2];
            outp[(c0 + 8) * HD + d0 + 1] = acc[ni][3];
        }
    }
}

// ---------------- combine, modulate, softmax ----------------
__global__ void softmax_kernel(const float* __restrict__ temp, const float* __restrict__ d_l) {
    __shared__ float S[HD * HD];
    int bh = blockIdx.x;
    int b = bh >> 3, h = bh & 7;
    int t = threadIdx.x;
    float tscale = temp[h] * d_l[b];
    for (int idx = t; idx < HD * HD; idx += 256) {
        const float* pp = g_attn_part + (size_t)bh * KSPLIT * (HD * HD) + idx;
        float s = 0.f;
        #pragma unroll
        for (int sp = 0; sp < KSPLIT; sp++) s += pp[(size_t)sp * (HD * HD)];
        int c = idx / HD, d = idx % HD;
        float nq = fmaxf(sqrtf(g_norm2[b * 768 + h * HD + c]), EPSV);
        float nk = fmaxf(sqrtf(g_norm2[b * 768 + C + h * HD + d]), EPSV);
        S[idx] = s / (nq * nk) * tscale * g_dcp[b * C + h * HD + c];
    }
    __syncthreads();
    if (t < HD) {
        float mx = -1e30f;
        for (int d = 0; d < HD; d++) mx = fmaxf(mx, S[t * HD + d]);
        float sum = 0.f;
        for (int d = 0; d < HD; d++) sum += expf(S[t * HD + d] - mx);
        float inv = 1.f / sum;
        for (int d = 0; d < HD; d++)
            g_attn[(size_t)bh * (HD * HD) + t * HD + d] = expf(S[t * HD + d] - mx) * inv;
    }
}

// ---------------- attn @ v: tensor-core (M=48, K=48), fp16 in/out ----------------
#define AVP 136
__global__ void __launch_bounds__(192) av_tc_kernel(const __half* __restrict__ dwbuf,
                                                    __half* __restrict__ oh) {
    __shared__ __half As[HD * 56];
    __shared__ __half vs[HD * AVP];
    int bh = blockIdx.y;
    int b = bh >> 3, h = bh & 7;
    const __half* vp = dwbuf + ((size_t)b * M3 + 2 * C + h * HD) * N;
    __half* op = oh + ((size_t)b * C + h * HD) * N;
    int t = threadIdx.x, lane = t & 31, w = t >> 5;
    int mi = w % 3, nh = w / 3;

    const float* ap = g_attn + (size_t)bh * (HD * HD);
    for (int i = t; i < HD * HD; i += 192) {
        int c = i / HD, d = i % HD;
        As[c * 56 + d] = __float2half(ap[i]);
    }
    __syncthreads();

    int n0 = blockIdx.x * 512;
    for (int chunk = 0; chunk < 4; chunk++) {
        int off = n0 + chunk * 128;
        for (int i = t; i < HD * 16; i += 192) {
            int d = i >> 4, c16 = (i & 15) * 8;
            *(uint4*)&vs[d * AVP + c16] = *(const uint4*)(vp + (size_t)d * N + off + c16);
        }
        __syncthreads();

        float acc[8][4];
        #pragma unroll
        for (int ni = 0; ni < 8; ni++)
            #pragma unroll
            for (int r = 0; r < 4; r++) acc[ni][r] = 0.f;

        #pragma unroll
        for (int kk2 = 0; kk2 < 3; kk2++) {
            int kk = kk2 * 16;
            uint32_t af[4];
            ldsm4(af, (uint32_t)__cvta_generic_to_shared(
                &As[(mi * 16 + (lane & 15)) * 56 + kk + ((lane >> 4) << 3)]));
            #pragma unroll
            for (int ni = 0; ni < 8; ni++) {
                uint32_t bf[2];
                ldsm2t(bf, (uint32_t)__cvta_generic_to_shared(
                    &vs[(kk + (lane & 15)) * AVP + nh * 64 + ni * 8]));
                mma16816h(acc[ni], af, bf);
            }
        }

        int r = lane >> 2;
        int c1 = mi * 16 + r, c2 = c1 + 8;
        #pragma unroll
        for (int ni = 0; ni < 8; ni++) {
            int col = off + nh * 64 + ni * 8 + (lane & 3) * 2;
            *(__half2*)&op[(size_t)c1 * N + col] = __floats2half2_rn(acc[ni][0], acc[ni][1]);
            *(__half2*)&op[(size_t)c2 * N + col] = __floats2half2_rn(acc[ni][2], acc[ni][3]);
        }
        __syncthreads();
    }
}

// ---------------- launch ----------------
extern "C" void kernel_launch(void* const* d_in, const int* in_sizes, int n_in,
                              void* d_out, int out_size) {
    const float* inputs  = (const float*)d_in[0];
    const float* d_c     = (const float*)d_in[1];
    const float* d_l     = (const float*)d_in[2];
    const float* temp    = (const float*)d_in[3];
    const float* prj_w   = (const float*)d_in[4];
    const float* prj_b   = (const float*)d_in[5];
    const float* dp_w1   = (const float*)d_in[6];
    const float* dp_b1   = (const float*)d_in[7];
    const float* dp_w2   = (const float*)d_in[8];
    const float* dp_b2   = (const float*)d_in[9];
    const float* wq_pw   = (const float*)d_in[10];
    const float* wq_pw_b = (const float*)d_in[11];
    const float* wq_dw   = (const float*)d_in[12];
    const float* wq_dw_b = (const float*)d_in[13];
    const float* wk_pw   = (const float*)d_in[14];
    const float* wk_pw_b = (const float*)d_in[15];
    const float* wk_dw   = (const float*)d_in[16];
    const float* wk_dw_b = (const float*)d_in[17];
    const float* wv_pw   = (const float*)d_in[18];
    const float* wv_pw_b = (const float*)d_in[19];
    const float* wv_dw   = (const float*)d_in[20];
    const float* wv_dw_b = (const float*)d_in[21];
    float* outp = (float*)d_out;

    __half *p_Whi, *p_Phi, *p_Xh, *p_avh, *p_pw, *p_dw;
    float *p_ball;
    cudaGetSymbolAddress((void**)&p_Whi, g_Whi);
    cudaGetSymbolAddress((void**)&p_Phi, g_Phi);
    cudaGetSymbolAddress((void**)&p_Xh, g_Xh);
    cudaGetSymbolAddress((void**)&p_avh, g_avh);
    cudaGetSymbolAddress((void**)&p_ball, g_ball);
    cudaGetSymbolAddress((void**)&p_pw, g_pw);
    cudaGetSymbolAddress((void**)&p_dw, g_dw);

    cudaFuncSetAttribute(gemm_tc_kernel,
                         cudaFuncAttributeMaxDynamicSharedMemorySize, GEMM_SMEM);

    pack_weights<<<(C * C + 255) / 256, 256>>>(
        wq_pw, wq_pw_b, wq_dw, wq_dw_b,
        wk_pw, wk_pw_b, wk_dw, wk_dw_b,
        wv_pw, wv_pw_b, wv_dw, wv_dw_b, prj_w);

    dcp_kernel<<<B, C>>>(d_c, dp_w1, dp_b1, dp_w2, dp_b2);

    split_kernel<<<(B * C * N / 4 + 255) / 256, 256>>>(inputs, p_Xh, B * C * N / 4);

    // QKV GEMM: single-product -> fp16 output
    gemm_tc_kernel<<<dim3(N / BN, M3 / BM, B), 256, GEMM_SMEM>>>(
        p_Whi, p_ball, p_Xh, nullptr, p_pw, M3);

    dwconv_kernel<<<dim3(HW / 16, B * M3), dim3(32, 8)>>>(p_pw, p_dw);

    qk_tc_kernel<<<dim3(KSPLIT, B * HEADS), 192>>>(p_dw);

    softmax_kernel<<<B * HEADS, 256>>>(temp, d_l);

    av_tc_kernel<<<dim3(N / 512, B * HEADS), 192>>>(p_dw, p_avh);

    // projection GEMM: single-product -> fp32 output
    gemm_tc_kernel<<<dim3(N / BN, C / BM, B), 256, GEMM_SMEM>>>(
        p_Phi, prj_b, p_avh, outp, nullptr, C);
}